// round 11
// baseline (speedup 1.0000x reference)
#include <cuda_runtime.h>
#include <cstdint>

// ======================= problem constants =======================
constexpr int N_ROWS = 16384;   // M
constexpr int D_DIM  = 2048;    // K
constexpr int V_DIM  = 8192;    // N (argmax axis)
constexpr int BM = 256, BN = 128;
constexpr int BK = 64;                    // 64 s8 = 64B per row-chunk
constexpr int KITER = D_DIM / BK;         // 32
constexpr int MT_G = N_ROWS / BM;         // 64
constexpr int NT_G = V_DIM / BN;          // 64
constexpr int NTHREADS = 512;             // 16 warps (4m x 4n), warp tile 64x32
constexpr int NSTAGE = 3;
constexpr int SLOTS = 8;                  // candidate slots per (row, tile)
constexpr float TAU = 5.0f;               // ~6 sigma of pairwise int8 screen error

constexpr int ASTRIDE = 80;                          // 64B data + 16B pad (conflict-free ldmatrix)
constexpr int STAGE_BYTES = (BM + BN) * ASTRIDE;     // 30720
constexpr int SMEM_BYTES = NSTAGE * STAGE_BYTES;     // 92160

// epilogue overlay offsets (reuse stage smem after mainloop)
constexpr int EP_RMAX = 0;                       // float[256][4]
constexpr int EP_THR  = EP_RMAX + 256 * 4 * 4;   // float[256]
constexpr int EP_CNT  = EP_THR + 256 * 4;        // int[256]

// ======================= device scratch (no cudaMalloc allowed) =======================
__device__ int8_t g_xq [(size_t)N_ROWS * D_DIM];   // x int8 (per-row scale)
__device__ int8_t g_dq [(size_t)V_DIM * D_DIM];    // di^T int8 (per-row scale), K-major
__device__ float  g_dtf[(size_t)V_DIM * D_DIM];    // di^T fp32 (rescore source + quant source)
__device__ float  g_sx [N_ROWS];                   // maxabs/127 for x rows
__device__ float  g_sd [V_DIM];                    // maxabs/127 for di^T rows
__device__ float g_tmax[N_ROWS * NT_G];
__device__ int   g_cnt [N_ROWS * NT_G];
__device__ int   g_ccol[N_ROWS * NT_G * SLOTS];
__device__ float g_cval[N_ROWS * NT_G * SLOTS];

// ======================= helpers =======================
__device__ __forceinline__ uint32_t smem_u32(const void* p) {
    uint32_t a;
    asm("{ .reg .u64 t; cvta.to.shared.u64 t, %1; cvt.u32.u64 %0, t; }" : "=r"(a) : "l"(p));
    return a;
}
__device__ __forceinline__ void cp_async16(uint32_t dst, const void* src) {
    asm volatile("cp.async.cg.shared.global [%0], [%1], 16;" :: "r"(dst), "l"(src) : "memory");
}
__device__ __forceinline__ void cp_commit() { asm volatile("cp.async.commit_group;" ::: "memory"); }
template <int N> __device__ __forceinline__ void cp_wait() {
    asm volatile("cp.async.wait_group %0;" :: "n"(N) : "memory");
}
__device__ __forceinline__ void ldmx4(uint32_t& r0, uint32_t& r1, uint32_t& r2, uint32_t& r3,
                                      uint32_t addr) {
    asm volatile("ldmatrix.sync.aligned.m8n8.x4.shared.b16 {%0,%1,%2,%3}, [%4];"
                 : "=r"(r0), "=r"(r1), "=r"(r2), "=r"(r3) : "r"(addr));
}
// s8 x s8 -> s32 accumulate, m16n8k32
__device__ __forceinline__ void mma_s8(int& c0, int& c1, int& c2, int& c3,
                                       uint32_t a0, uint32_t a1, uint32_t a2, uint32_t a3,
                                       uint32_t b0, uint32_t b1) {
    asm volatile("mma.sync.aligned.m16n8k32.row.col.s32.s8.s8.s32 "
                 "{%0,%1,%2,%3}, {%4,%5,%6,%7}, {%8,%9}, {%0,%1,%2,%3};"
                 : "+r"(c0), "+r"(c1), "+r"(c2), "+r"(c3)
                 : "r"(a0), "r"(a1), "r"(a2), "r"(a3), "r"(b0), "r"(b1));
}

__device__ __forceinline__ int8_t q8(float v, float scale) {
    int t = __float2int_rn(v * scale);
    t = max(-127, min(127, t));
    return (int8_t)t;
}

// ======================= preprocessing kernels =======================
// fp32 rows -> int8 rows with per-row symmetric scale. One warp per row of 2048.
__global__ void __launch_bounds__(256) quant_rows_kernel(const float* __restrict__ src,
                                                         int8_t* __restrict__ dst,
                                                         float* __restrict__ sinv) {
    const int row = blockIdx.x * 8 + (threadIdx.x >> 5);
    const int lane = threadIdx.x & 31;
    const float4* sr = (const float4*)(src + (size_t)row * D_DIM);
    float4 v[16];
    float mx = 1e-20f;
    #pragma unroll
    for (int i = 0; i < 16; i++) {
        v[i] = sr[lane + 32 * i];
        mx = fmaxf(mx, fmaxf(fmaxf(fabsf(v[i].x), fabsf(v[i].y)),
                             fmaxf(fabsf(v[i].z), fabsf(v[i].w))));
    }
    #pragma unroll
    for (int off = 16; off > 0; off >>= 1)
        mx = fmaxf(mx, __shfl_xor_sync(0xffffffffu, mx, off));
    const float scale = 127.0f / mx;
    if (lane == 0) sinv[row] = mx / 127.0f;
    uint32_t* dw = (uint32_t*)(dst + (size_t)row * D_DIM);
    #pragma unroll
    for (int i = 0; i < 16; i++) {
        uchar4 p;
        p.x = (uint8_t)q8(v[i].x, scale);
        p.y = (uint8_t)q8(v[i].y, scale);
        p.z = (uint8_t)q8(v[i].z, scale);
        p.w = (uint8_t)q8(v[i].w, scale);
        dw[lane + 32 * i] = *(uint32_t*)&p;
    }
}

__global__ void __launch_bounds__(256) transpose_di_kernel(const float* __restrict__ di) {
    __shared__ float t[32][33];
    const int v0 = blockIdx.x * 32, k0 = blockIdx.y * 32;
    const int tx = threadIdx.x, ty = threadIdx.y;
    #pragma unroll
    for (int i = 0; i < 4; i++)
        t[ty + 8 * i][tx] = di[(size_t)(k0 + ty + 8 * i) * V_DIM + v0 + tx];
    __syncthreads();
    #pragma unroll
    for (int i = 0; i < 4; i++)
        g_dtf[(size_t)(v0 + ty + 8 * i) * D_DIM + k0 + tx] = t[tx][ty + 8 * i];
}

// ======================= IMMA s8 GEMM + candidate epilogue =======================
__global__ void __launch_bounds__(NTHREADS, 1) gemm_s8_kernel() {
    extern __shared__ char smem[];
    const uint32_t sbase = smem_u32(smem);
    const int tid = threadIdx.x;
    const int wid = tid >> 5, lane = tid & 31;
    const int m0 = blockIdx.x * BM;
    const int v0 = blockIdx.y * BN;

    const int wm = wid >> 2;       // 0..3 : 64-row slab
    const int wn = wid & 3;        // 0..3 : 32-col slab

    uint32_t a_off[NSTAGE], b_off[NSTAGE];
    #pragma unroll
    for (int s = 0; s < NSTAGE; s++) {
        a_off[s] = sbase + s * STAGE_BYTES;
        b_off[s] = a_off[s] + BM * ASTRIDE;
    }

    const int8_t* agp = g_xq + (size_t)m0 * D_DIM;
    const int8_t* bgp = g_dq + (size_t)v0 * D_DIM;

    int acc[4][4][4];
    #pragma unroll
    for (int i = 0; i < 4; i++)
        #pragma unroll
        for (int j = 0; j < 4; j++)
            #pragma unroll
            for (int e = 0; e < 4; e++) acc[i][j][e] = 0;

    const int lm_row = lane & 15;
    const int lm_hi  = (lane >> 4) * 16;

    // A: 1024 16B chunks (256 rows x 4), 2 per thread. B: 512 chunks, 1 per thread.
    auto load_stage = [&](int slot, int kc) {
        const size_t kb = (size_t)kc * BK;
        #pragma unroll
        for (int i = 0; i < 2; i++) {
            const int idx = tid + NTHREADS * i;
            const int row = idx >> 2, ch = (idx & 3) * 16;
            cp_async16(a_off[slot] + row * ASTRIDE + ch,
                       agp + (size_t)row * D_DIM + kb + ch);
        }
        {
            const int row = tid >> 2, ch = (tid & 3) * 16;
            cp_async16(b_off[slot] + row * ASTRIDE + ch,
                       bgp + (size_t)row * D_DIM + kb + ch);
        }
    };

    load_stage(0, 0); cp_commit();
    load_stage(1, 1); cp_commit();

    #pragma unroll 1
    for (int k = 0; k < KITER; k++) {
        cp_wait<1>();
        __syncthreads();
        if (k + 2 < KITER) load_stage((k + 2) % NSTAGE, k + 2);
        cp_commit();

        const int s = k % NSTAGE;
        const uint32_t abase = a_off[s] + (wm * 64 + lm_row) * ASTRIDE + lm_hi;
        const uint32_t bbase = b_off[s] + (wn * 32 + lm_row) * ASTRIDE + lm_hi;

        #pragma unroll
        for (int ks = 0; ks < 2; ks++) {
            const uint32_t ko = ks * 32;       // 32 s8 = 32B per k-step
            uint32_t a[4][4];
            #pragma unroll
            for (int mt = 0; mt < 4; mt++)
                ldmx4(a[mt][0], a[mt][1], a[mt][2], a[mt][3],
                      abase + mt * 16 * ASTRIDE + ko);
            uint32_t b[2][4];
            #pragma unroll
            for (int nh = 0; nh < 2; nh++)
                ldmx4(b[nh][0], b[nh][1], b[nh][2], b[nh][3],
                      bbase + nh * 16 * ASTRIDE + ko);
            #pragma unroll
            for (int mt = 0; mt < 4; mt++)
                #pragma unroll
                for (int nt = 0; nt < 4; nt++) {
                    const uint32_t b0 = (nt & 1) ? b[nt >> 1][1] : b[nt >> 1][0];
                    const uint32_t b1 = (nt & 1) ? b[nt >> 1][3] : b[nt >> 1][2];
                    mma_s8(acc[mt][nt][0], acc[mt][nt][1], acc[mt][nt][2], acc[mt][nt][3],
                           a[mt][0], a[mt][1], a[mt][2], a[mt][3], b0, b1);
                }
        }
    }
    cp_wait<0>();
    __syncthreads();   // stage smem dead; overlay epilogue arrays

    float* rmax4 = (float*)(smem + EP_RMAX);   // [row][wn]
    float* thr_s = (float*)(smem + EP_THR);    // [row]
    int*   cnt_s = (int*)  (smem + EP_CNT);    // [row]

    const int rq = lane >> 2;          // 0..7
    const int cq = (lane & 3) * 2;     // 0,2,4,6

    // per-row scales (2 row instances per mt) and per-col scales (8 cols of this thread)
    float sd_c[4][2];
    #pragma unroll
    for (int nt = 0; nt < 4; nt++) {
        sd_c[nt][0] = __ldg(&g_sd[v0 + wn * 32 + nt * 8 + cq]);
        sd_c[nt][1] = __ldg(&g_sd[v0 + wn * 32 + nt * 8 + cq + 1]);
    }

    // pass 1: per-thread per-row max of scaled scores, fold across lane quads
    #pragma unroll
    for (int mt = 0; mt < 4; mt++) {
        #pragma unroll
        for (int h = 0; h < 2; h++) {
            const int row = wm * 64 + mt * 16 + rq + h * 8;
            const float sx = __ldg(&g_sx[m0 + row]);
            float m = -3.4e38f;
            #pragma unroll
            for (int nt = 0; nt < 4; nt++) {
                m = fmaxf(m, (float)acc[mt][nt][2 * h + 0] * sx * sd_c[nt][0]);
                m = fmaxf(m, (float)acc[mt][nt][2 * h + 1] * sx * sd_c[nt][1]);
            }
            #pragma unroll
            for (int off = 1; off < 4; off <<= 1)
                m = fmaxf(m, __shfl_xor_sync(0xffffffffu, m, off));
            if ((lane & 3) == 0) rmax4[row * 4 + wn] = m;
        }
    }
    __syncthreads();

    if (tid < BM) {
        const float mx = fmaxf(fmaxf(rmax4[tid * 4 + 0], rmax4[tid * 4 + 1]),
                               fmaxf(rmax4[tid * 4 + 2], rmax4[tid * 4 + 3]));
        thr_s[tid] = mx - TAU;
        cnt_s[tid] = 0;
        g_tmax[(m0 + tid) * NT_G + blockIdx.y] = mx;
    }
    __syncthreads();

    // pass 2: candidate extraction
    #pragma unroll
    for (int mt = 0; mt < 4; mt++) {
        #pragma unroll
        for (int h = 0; h < 2; h++) {
            const int row = wm * 64 + mt * 16 + rq + h * 8;
            const float sx = __ldg(&g_sx[m0 + row]);
            const float th = thr_s[row];
            const int base = ((m0 + row) * NT_G + blockIdx.y) * SLOTS;
            #pragma unroll
            for (int nt = 0; nt < 4; nt++) {
                #pragma unroll
                for (int j = 0; j < 2; j++) {
                    const float v = (float)acc[mt][nt][2 * h + j] * sx * sd_c[nt][j];
                    if (v >= th) {
                        const int p = atomicAdd(&cnt_s[row], 1);
                        if (p < SLOTS) {
                            g_ccol[base + p] = v0 + wn * 32 + nt * 8 + cq + j;
                            g_cval[base + p] = v;
                        }
                    }
                }
            }
        }
    }
    __syncthreads();
    if (tid < BM)
        g_cnt[(m0 + tid) * NT_G + blockIdx.y] = min(cnt_s[tid], SLOTS);
}

// ======================= combine + exact fp32 rescore =======================
__global__ void __launch_bounds__(256) rescore_kernel(const float* __restrict__ x,
                                                      float* __restrict__ out) {
    const int r = (blockIdx.x * 256 + threadIdx.x) >> 5;
    const int lane = threadIdx.x & 31;
    if (r >= N_ROWS) return;

    float gm = fmaxf(g_tmax[r * NT_G + lane], g_tmax[r * NT_G + lane + 32]);
    #pragma unroll
    for (int off = 16; off > 0; off >>= 1)
        gm = fmaxf(gm, __shfl_xor_sync(0xffffffffu, gm, off));
    const float thr = gm - TAU;

    int q = 0, mycol = 0x7fffffff;
    #pragma unroll
    for (int h = 0; h < 2; h++) {
        const int nt = lane + 32 * h;
        const int c_ = g_cnt[r * NT_G + nt];
        const int base = (r * NT_G + nt) * SLOTS;
        for (int s = 0; s < c_; s++) {
            if (g_cval[base + s] >= thr) {
                mycol = min(mycol, g_ccol[base + s]);
                q++;
            }
        }
    }
    int tot = q;
    int col1 = mycol;
    #pragma unroll
    for (int off = 16; off > 0; off >>= 1) {
        tot  += __shfl_xor_sync(0xffffffffu, tot, off);
        col1 = min(col1, __shfl_xor_sync(0xffffffffu, col1, off));
    }
    if (tot == 1) {
        if (lane == 0) out[r] = (float)col1;
        return;
    }

    float bestv = -3.4e38f;
    int bestc = 0x7fffffff;
    const float4* xr = (const float4*)(x + (size_t)r * D_DIM);
    for (int nt = 0; nt < NT_G; nt++) {
        const int c_ = g_cnt[r * NT_G + nt];
        const int base = (r * NT_G + nt) * SLOTS;
        for (int s = 0; s < c_; s++) {
            if (g_cval[base + s] < thr) continue;
            const int col = g_ccol[base + s];
            const float4* dv = (const float4*)(g_dtf + (size_t)col * D_DIM);
            float a_ = 0.f;
            #pragma unroll
            for (int i = 0; i < 16; i++) {
                float4 a = xr[lane + 32 * i];
                float4 b = dv[lane + 32 * i];
                a_ += a.x * b.x + a.y * b.y + a.z * b.z + a.w * b.w;
            }
            #pragma unroll
            for (int off = 16; off > 0; off >>= 1)
                a_ += __shfl_xor_sync(0xffffffffu, a_, off);
            if (a_ > bestv || (a_ == bestv && col < bestc)) { bestv = a_; bestc = col; }
        }
    }
    if (lane == 0) out[r] = (float)bestc;
}

// ======================= launch =======================
extern "C" void kernel_launch(void* const* d_in, const int* in_sizes, int n_in,
                              void* d_out, int out_size)
{
    const float* x  = (const float*)d_in[0];   // [N, D]
    const float* di = (const float*)d_in[1];   // [D, V]
    float* out = (float*)d_out;

    static bool attr_done = false;
    if (!attr_done) {
        cudaFuncSetAttribute(gemm_s8_kernel,
                             cudaFuncAttributeMaxDynamicSharedMemorySize, SMEM_BYTES);
        attr_done = true;
    }

    int8_t* d_xq; cudaGetSymbolAddress((void**)&d_xq, g_xq);
    int8_t* d_dq; cudaGetSymbolAddress((void**)&d_dq, g_dq);
    float*  d_dtf; cudaGetSymbolAddress((void**)&d_dtf, g_dtf);
    float*  d_sx; cudaGetSymbolAddress((void**)&d_sx, g_sx);
    float*  d_sd; cudaGetSymbolAddress((void**)&d_sd, g_sd);

    quant_rows_kernel<<<N_ROWS / 8, 256>>>(x, d_xq, d_sx);
    transpose_di_kernel<<<dim3(V_DIM / 32, D_DIM / 32), dim3(32, 8)>>>(di);
    quant_rows_kernel<<<V_DIM / 8, 256>>>(d_dtf, d_dq, d_sd);
    gemm_s8_kernel<<<dim3(MT_G, NT_G), NTHREADS, SMEM_BYTES>>>();
    rescore_kernel<<<N_ROWS / 8, 256>>>(x, out);
}

// round 12
// speedup vs baseline: 2.4214x; 2.4214x over previous
#include <cuda_runtime.h>
#include <cuda_fp16.h>
#include <cstdint>

// ======================= problem constants =======================
constexpr int N_ROWS = 16384;   // M
constexpr int D_DIM  = 2048;    // K
constexpr int V_DIM  = 8192;    // N (argmax axis)
constexpr int BM = 128, BN = 128, BK = 64;
constexpr int KITER = D_DIM / BK;         // 32
constexpr int MT_G = N_ROWS / BM;         // 128
constexpr int NT_G = V_DIM / BN;          // 64
constexpr int NSTAGE = 3;
constexpr int SLOTS = 4;                  // candidate slots per (row, tile)
constexpr float TAU = 3.0f;               // ~12 sigma of f16-accum screen error

constexpr int ASTRIDE = 144;                      // 128B data + 16B pad (odd 16B-chunk stride -> conflict-free)
constexpr int STAGE_BYTES = 2 * BM * ASTRIDE;     // 36864
constexpr int SMEM_BYTES = NSTAGE * STAGE_BYTES;  // 110592 -> 2 CTAs/SM

// epilogue overlay offsets (reuses stage smem after mainloop)
constexpr int EP_RMAX = 0;                  // float[128][4]
constexpr int EP_THR  = EP_RMAX + 128 * 4 * 4;   // float[128]
constexpr int EP_CNT  = EP_THR + 128 * 4;        // int[128]

// ======================= device scratch (no cudaMalloc allowed) =======================
__device__ __half g_xh [(size_t)N_ROWS * D_DIM];   // x in f16
__device__ __half g_dth[(size_t)V_DIM * D_DIM];    // di^T f16 (K-major)
__device__ float  g_dtf[(size_t)V_DIM * D_DIM];    // di^T fp32 (rescore)
__device__ float g_tmax[N_ROWS * NT_G];
__device__ int   g_cnt [N_ROWS * NT_G];
__device__ int   g_ccol[N_ROWS * NT_G * SLOTS];
__device__ float g_cval[N_ROWS * NT_G * SLOTS];

// ======================= helpers =======================
__device__ __forceinline__ uint32_t smem_u32(const void* p) {
    uint32_t a;
    asm("{ .reg .u64 t; cvta.to.shared.u64 t, %1; cvt.u32.u64 %0, t; }" : "=r"(a) : "l"(p));
    return a;
}
__device__ __forceinline__ void cp_async16(uint32_t dst, const void* src) {
    asm volatile("cp.async.cg.shared.global [%0], [%1], 16;" :: "r"(dst), "l"(src) : "memory");
}
__device__ __forceinline__ void cp_commit() { asm volatile("cp.async.commit_group;" ::: "memory"); }
template <int N> __device__ __forceinline__ void cp_wait() {
    asm volatile("cp.async.wait_group %0;" :: "n"(N) : "memory");
}
__device__ __forceinline__ void ldmx4(uint32_t& r0, uint32_t& r1, uint32_t& r2, uint32_t& r3,
                                      uint32_t addr) {
    asm volatile("ldmatrix.sync.aligned.m8n8.x4.shared.b16 {%0,%1,%2,%3}, [%4];"
                 : "=r"(r0), "=r"(r1), "=r"(r2), "=r"(r3) : "r"(addr));
}
// f16 x f16 -> f16 accumulate (packed f16x2 c regs)
__device__ __forceinline__ void mma16816_f16(uint32_t& c0, uint32_t& c1,
                                             uint32_t a0, uint32_t a1, uint32_t a2, uint32_t a3,
                                             uint32_t b0, uint32_t b1) {
    asm volatile("mma.sync.aligned.m16n8k16.row.col.f16.f16.f16.f16 "
                 "{%0,%1}, {%2,%3,%4,%5}, {%6,%7}, {%0,%1};"
                 : "+r"(c0), "+r"(c1)
                 : "r"(a0), "r"(a1), "r"(a2), "r"(a3), "r"(b0), "r"(b1));
}

// ======================= conversion kernels =======================
__global__ void __launch_bounds__(256) conv_x_kernel(const float* __restrict__ x) {
    size_t i = (size_t)blockIdx.x * 256 + threadIdx.x;     // float4 index
    float4 v = ((const float4*)x)[i];
    __half2* o = (__half2*)g_xh;
    o[2 * i + 0] = __floats2half2_rn(v.x, v.y);
    o[2 * i + 1] = __floats2half2_rn(v.z, v.w);
}

__global__ void __launch_bounds__(256) transpose_di_kernel(const float* __restrict__ di) {
    __shared__ float t[32][33];
    const int v0 = blockIdx.x * 32, k0 = blockIdx.y * 32;
    const int tx = threadIdx.x, ty = threadIdx.y;
    #pragma unroll
    for (int i = 0; i < 4; i++)
        t[ty + 8 * i][tx] = di[(size_t)(k0 + ty + 8 * i) * V_DIM + v0 + tx];
    __syncthreads();
    #pragma unroll
    for (int i = 0; i < 4; i++) {
        float val = t[tx][ty + 8 * i];
        size_t o = (size_t)(v0 + ty + 8 * i) * D_DIM + k0 + tx;
        g_dtf[o] = val;
        g_dth[o] = __float2half_rn(val);
    }
}

// ======================= HMMA f16 GEMM (BK=64) + register-resident candidate epilogue =======================
__global__ void __launch_bounds__(256, 2) gemm_hmma_kernel() {
    extern __shared__ char smem[];
    const uint32_t sbase = smem_u32(smem);
    const int tid = threadIdx.x;
    const int wid = tid >> 5, lane = tid & 31;
    const int m0 = blockIdx.x * BM;
    const int v0 = blockIdx.y * BN;

    const int wm = wid >> 2;       // 0..1 : 64-row slab
    const int wn = wid & 3;        // 0..3 : 32-col slab

    uint32_t a_off[NSTAGE], b_off[NSTAGE];
    #pragma unroll
    for (int s = 0; s < NSTAGE; s++) {
        a_off[s] = sbase + s * STAGE_BYTES;
        b_off[s] = a_off[s] + BM * ASTRIDE;
    }

    // gmem->smem map: 128 rows x 8 x 16B chunks = 1024 chunks per operand; 4/thread
    const __half* agp = g_xh  + (size_t)m0 * D_DIM;
    const __half* bgp = g_dth + (size_t)v0 * D_DIM;

    // f16 accumulators: [mt][nt][half] where half 0 = row rq, 1 = row rq+8
    uint32_t acc[4][4][2];
    #pragma unroll
    for (int i = 0; i < 4; i++)
        #pragma unroll
        for (int j = 0; j < 4; j++) { acc[i][j][0] = 0u; acc[i][j][1] = 0u; }

    const int lm_row = lane & 15;
    const int lm_hi  = (lane >> 4) * 16;

    auto load_stage = [&](int slot, int kc) {
        const size_t kb = (size_t)kc * BK;          // element offset in K
        #pragma unroll
        for (int i = 0; i < 4; i++) {
            const int idx = tid + 256 * i;
            const int row = idx >> 3;               // 0..127
            const int che = (idx & 7) * 8;          // chunk offset in elements (16B = 8 halves)
            cp_async16(a_off[slot] + row * ASTRIDE + che * 2,
                       agp + (size_t)row * D_DIM + kb + che);
        }
        #pragma unroll
        for (int i = 0; i < 4; i++) {
            const int idx = tid + 256 * i;
            const int row = idx >> 3;
            const int che = (idx & 7) * 8;
            cp_async16(b_off[slot] + row * ASTRIDE + che * 2,
                       bgp + (size_t)row * D_DIM + kb + che);
        }
    };

    load_stage(0, 0); cp_commit();
    load_stage(1, 1); cp_commit();

    #pragma unroll 1
    for (int k = 0; k < KITER; k++) {
        cp_wait<1>();
        __syncthreads();
        if (k + 2 < KITER) load_stage((k + 2) % NSTAGE, k + 2);
        cp_commit();

        const int s = k % NSTAGE;
        const uint32_t abase = a_off[s] + (wm * 64 + lm_row) * ASTRIDE + lm_hi;
        const uint32_t bbase = b_off[s] + (wn * 32 + lm_row) * ASTRIDE + lm_hi;

        #pragma unroll
        for (int ks = 0; ks < 4; ks++) {
            const uint32_t ko = ks * 32;            // 16 f16 = 32B per k-step
            uint32_t a[4][4];
            #pragma unroll
            for (int mt = 0; mt < 4; mt++)
                ldmx4(a[mt][0], a[mt][1], a[mt][2], a[mt][3],
                      abase + mt * 16 * ASTRIDE + ko);
            uint32_t b[2][4];
            #pragma unroll
            for (int nh = 0; nh < 2; nh++)
                ldmx4(b[nh][0], b[nh][1], b[nh][2], b[nh][3],
                      bbase + nh * 16 * ASTRIDE + ko);
            #pragma unroll
            for (int mt = 0; mt < 4; mt++)
                #pragma unroll
                for (int nt = 0; nt < 4; nt++) {
                    const uint32_t b0 = (nt & 1) ? b[nt >> 1][1] : b[nt >> 1][0];
                    const uint32_t b1 = (nt & 1) ? b[nt >> 1][3] : b[nt >> 1][2];
                    mma16816_f16(acc[mt][nt][0], acc[mt][nt][1],
                                 a[mt][0], a[mt][1], a[mt][2], a[mt][3], b0, b1);
                }
        }
    }
    cp_wait<0>();
    __syncthreads();   // stage smem dead; overlay epilogue arrays

    float* rmax4 = (float*)(smem + EP_RMAX);   // [row][wn]
    float* thr_s = (float*)(smem + EP_THR);    // [row]
    int*   cnt_s = (int*)  (smem + EP_CNT);    // [row]

    const int rq = lane >> 2;          // 0..7
    const int cq = (lane & 3) * 2;     // 0,2,4,6

    // per-thread per-row max over this warp's 32 cols, f16 -> f32
    #pragma unroll
    for (int mt = 0; mt < 4; mt++) {
        #pragma unroll
        for (int h = 0; h < 2; h++) {
            float m = -3.4e38f;
            #pragma unroll
            for (int nt = 0; nt < 4; nt++) {
                const __half2 hv = *(const __half2*)&acc[mt][nt][h];
                m = fmaxf(m, fmaxf(__low2float(hv), __high2float(hv)));
            }
            #pragma unroll
            for (int off = 1; off < 4; off <<= 1)
                m = fmaxf(m, __shfl_xor_sync(0xffffffffu, m, off));
            if ((lane & 3) == 0) {
                const int row = wm * 64 + mt * 16 + rq + h * 8;
                rmax4[row * 4 + wn] = m;
            }
        }
    }
    __syncthreads();

    if (tid < BM) {
        const float mx = fmaxf(fmaxf(rmax4[tid * 4 + 0], rmax4[tid * 4 + 1]),
                               fmaxf(rmax4[tid * 4 + 2], rmax4[tid * 4 + 3]));
        thr_s[tid] = mx - TAU;
        cnt_s[tid] = 0;
        g_tmax[(m0 + tid) * NT_G + blockIdx.y] = mx;
    }
    __syncthreads();

    // candidate extraction straight from registers
    #pragma unroll
    for (int mt = 0; mt < 4; mt++) {
        #pragma unroll
        for (int h = 0; h < 2; h++) {
            const int row = wm * 64 + mt * 16 + rq + h * 8;
            const float th = thr_s[row];
            const int base = ((m0 + row) * NT_G + blockIdx.y) * SLOTS;
            #pragma unroll
            for (int nt = 0; nt < 4; nt++) {
                const __half2 hv = *(const __half2*)&acc[mt][nt][h];
                const float v0f = __low2float(hv), v1f = __high2float(hv);
                if (v0f >= th) {
                    const int p = atomicAdd(&cnt_s[row], 1);
                    if (p < SLOTS) {
                        g_ccol[base + p] = v0 + wn * 32 + nt * 8 + cq;
                        g_cval[base + p] = v0f;
                    }
                }
                if (v1f >= th) {
                    const int p = atomicAdd(&cnt_s[row], 1);
                    if (p < SLOTS) {
                        g_ccol[base + p] = v0 + wn * 32 + nt * 8 + cq + 1;
                        g_cval[base + p] = v1f;
                    }
                }
            }
        }
    }
    __syncthreads();
    if (tid < BM)
        g_cnt[(m0 + tid) * NT_G + blockIdx.y] = min(cnt_s[tid], SLOTS);
}

// ======================= combine + exact fp32 rescore =======================
__global__ void __launch_bounds__(256) rescore_kernel(const float* __restrict__ x,
                                                      float* __restrict__ out) {
    const int r = (blockIdx.x * 256 + threadIdx.x) >> 5;
    const int lane = threadIdx.x & 31;
    if (r >= N_ROWS) return;

    float gm = fmaxf(g_tmax[r * NT_G + lane], g_tmax[r * NT_G + lane + 32]);
    #pragma unroll
    for (int off = 16; off > 0; off >>= 1)
        gm = fmaxf(gm, __shfl_xor_sync(0xffffffffu, gm, off));
    const float thr = gm - TAU;

    int q = 0, mycol = 0x7fffffff;
    #pragma unroll
    for (int h = 0; h < 2; h++) {
        const int nt = lane + 32 * h;
        const int c_ = g_cnt[r * NT_G + nt];
        const int base = (r * NT_G + nt) * SLOTS;
        for (int s = 0; s < c_; s++) {
            if (g_cval[base + s] >= thr) {
                mycol = min(mycol, g_ccol[base + s]);
                q++;
            }
        }
    }
    int tot = q;
    int col1 = mycol;
    #pragma unroll
    for (int off = 16; off > 0; off >>= 1) {
        tot  += __shfl_xor_sync(0xffffffffu, tot, off);
        col1 = min(col1, __shfl_xor_sync(0xffffffffu, col1, off));
    }
    if (tot == 1) {
        if (lane == 0) out[r] = (float)col1;
        return;
    }

    float bestv = -3.4e38f;
    int bestc = 0x7fffffff;
    const float4* xr = (const float4*)(x + (size_t)r * D_DIM);
    for (int nt = 0; nt < NT_G; nt++) {
        const int c_ = g_cnt[r * NT_G + nt];
        const int base = (r * NT_G + nt) * SLOTS;
        for (int s = 0; s < c_; s++) {
            if (g_cval[base + s] < thr) continue;
            const int col = g_ccol[base + s];
            const float4* dv = (const float4*)(g_dtf + (size_t)col * D_DIM);
            float a_ = 0.f;
            #pragma unroll
            for (int i = 0; i < 16; i++) {
                float4 a = xr[lane + 32 * i];
                float4 b = dv[lane + 32 * i];
                a_ += a.x * b.x + a.y * b.y + a.z * b.z + a.w * b.w;
            }
            #pragma unroll
            for (int off = 16; off > 0; off >>= 1)
                a_ += __shfl_xor_sync(0xffffffffu, a_, off);
            if (a_ > bestv || (a_ == bestv && col < bestc)) { bestv = a_; bestc = col; }
        }
    }
    if (lane == 0) out[r] = (float)bestc;
}

// ======================= launch =======================
extern "C" void kernel_launch(void* const* d_in, const int* in_sizes, int n_in,
                              void* d_out, int out_size)
{
    const float* x  = (const float*)d_in[0];   // [N, D]
    const float* di = (const float*)d_in[1];   // [D, V]
    float* out = (float*)d_out;

    static bool attr_done = false;
    if (!attr_done) {
        cudaFuncSetAttribute(gemm_hmma_kernel,
                             cudaFuncAttributeMaxDynamicSharedMemorySize, SMEM_BYTES);
        attr_done = true;
    }

    conv_x_kernel<<<(N_ROWS * D_DIM / 4) / 256, 256>>>(x);
    transpose_di_kernel<<<dim3(V_DIM / 32, D_DIM / 32), dim3(32, 8)>>>(di);
    gemm_hmma_kernel<<<dim3(MT_G, NT_G), 256, SMEM_BYTES>>>();
    rescore_kernel<<<N_ROWS / 8, 256>>>(x, out);
}